// round 2
// baseline (speedup 1.0000x reference)
#include <cuda_runtime.h>

// Problem geometry (fixed by the reference).
#define NCELLS (32 * 256 * 128)      // 1,048,576 polar cells per batch
#define NVOX   (320 * 320 * 80)      // 8,192,000 voxels per batch
#define BATCH  16
#define CPT    8

// Hot box: all atomic targets provably satisfy xi in [52,267], yi in [160,287],
// zi in [2,77] (from the analytic polar->cartesian map). Box below adds a
// 4-voxel margin on x/y and takes full z. Atomics touch ONLY the hot box, so
// the cold region can be zeroed CONCURRENTLY with the scatter.
#define YH0 156
#define YH1 292                       // exclusive; 136 rows
#define XH0 48
#define XH1 272                       // exclusive; 224 cols = 56 float4

#define HOT_F4_ROW ((XH1 - XH0) / 4)                  // 56
#define HOT_ROWS   (BATCH * 80 * (YH1 - YH0))         // 174,080
#define HOT_F4     (HOT_ROWS * HOT_F4_ROW)            // 9,748,480

#define FULLROWS      (320 - (YH1 - YH0))             // 184 full-width cold rows/slice
#define FULL_F4       (FULLROWS * 80)                 // 14,720
#define STRIP_F4_ROW  24                              // 2 x 48-float side strips
#define STRIP_F4      ((YH1 - YH0) * STRIP_F4_ROW)    // 3,264
#define SLICE_COLD_F4 (FULL_F4 + STRIP_F4)            // 17,984
#define NSLICES       (BATCH * 80)                    // 1,280
#define COLD_F4       (SLICE_COLD_F4 * NSLICES)       // 23,019,520

#define COLD_BLOCKS 2048u
#define SCAT_BLOCKS 8192u            // 512 per batch x 16

// ---------------------------------------------------------------------------
// Kernel 1: zero the hot box only (156 MB). Fast, pure write bandwidth.
__global__ void __launch_bounds__(256)
zero_hot(float4* __restrict__ out)
{
    const float4 z4 = make_float4(0.f, 0.f, 0.f, 0.f);
    for (unsigned t = blockIdx.x * 256u + threadIdx.x; t < HOT_F4;
         t += gridDim.x * 256u) {
        unsigned c   = t % HOT_F4_ROW;
        unsigned row = t / HOT_F4_ROW;
        unsigned b   = row / (80u * (YH1 - YH0));
        unsigned rem = row % (80u * (YH1 - YH0));
        unsigned z   = rem / (YH1 - YH0);
        unsigned y   = YH0 + rem % (YH1 - YH0);
        // float offset (((b*80+z)*320 + y)*320 + XH0) is divisible by 4
        unsigned f4  = ((b * 80u + z) * 320u + y) * 80u + (XH0 / 4) + c;
        out[f4] = z4;
    }
}

// ---------------------------------------------------------------------------
// Kernel 2 (fused): scatter blocks + cold-zero blocks interleaved 4:1 so both
// roles co-run on every SM wave. Scatter is L2-atomic bound (DRAM ~23%),
// cold-zero is DRAM-write bound -> complementary resources.
__global__ void __launch_bounds__(256)
scatter_and_cold(const float* __restrict__ in,
                 const int*   __restrict__ idx,
                 float*       __restrict__ out)
{
    unsigned q = blockIdx.x / 5u;
    unsigned r = blockIdx.x % 5u;

    if (r == 4u) {
        // ---- cold-zero role (2048 blocks): zero everything outside hot box.
        float4* o4 = reinterpret_cast<float4*>(out);
        const float4 z4 = make_float4(0.f, 0.f, 0.f, 0.f);
        for (unsigned t = q * 256u + threadIdx.x; t < COLD_F4;
             t += COLD_BLOCKS * 256u) {
            unsigned s = t / SLICE_COLD_F4;           // slice = b*80+z
            unsigned u = t % SLICE_COLD_F4;
            unsigned f4;
            if (u < FULL_F4) {                        // full-width rows
                unsigned yr = u / 80u, c = u % 80u;
                unsigned y  = (yr < YH0) ? yr : yr + (YH1 - YH0);
                f4 = s * 25600u + y * 80u + c;
            } else {                                  // side strips
                unsigned u2 = u - FULL_F4;
                unsigned y  = YH0 + u2 / STRIP_F4_ROW;
                unsigned c  = u2 % STRIP_F4_ROW;
                unsigned xf4 = (c < 12u) ? c : ((XH1 / 4) - 12u + c);
                f4 = s * 25600u + y * 80u + xf4;
            }
            o4[f4] = z4;
        }
    } else {
        // ---- scatter role (8192 blocks): run-length fused atomic scatter.
        unsigned sid  = q * 4u + r;                   // 0..8191
        unsigned b    = sid >> 9;                     // /512 -> batch
        unsigned blk  = sid & 511u;
        unsigned cell = (blk * 256u + threadIdx.x) * CPT;

        const int4* ip = reinterpret_cast<const int4*>(idx + cell);
        int4 i0 = ip[0];
        int4 i1 = ip[1];
        const float4* vp = reinterpret_cast<const float4*>(
            in + (size_t)b * NCELLS + cell);
        float4 v0 = vp[0];
        float4 v1 = vp[1];

        int   ind[CPT] = { i0.x, i0.y, i0.z, i0.w, i1.x, i1.y, i1.z, i1.w };
        float val[CPT] = { v0.x, v0.y, v0.z, v0.w, v1.x, v1.y, v1.z, v1.w };

        float* ob = out + (size_t)b * NVOX;

        int   cur = ind[0];
        float acc = val[0];
#pragma unroll
        for (int j = 1; j < CPT; j++) {
            if (ind[j] == cur) {
                acc += val[j];
            } else {
                atomicAdd(ob + cur, acc);             // no return -> REDG
                cur = ind[j];
                acc = val[j];
            }
        }
        atomicAdd(ob + cur, acc);
    }
}

extern "C" void kernel_launch(void* const* d_in, const int* in_sizes, int n_in,
                              void* d_out, int out_size)
{
    const float* polar = (const float*)d_in[0];   // [16,1,32,256,128] f32
    const int*   idx   = (const int*)  d_in[1];   // [1048576] int32
    float*       out   = (float*)d_out;           // [16,1,80,320,320] f32

    zero_hot<<<2048, 256>>>(reinterpret_cast<float4*>(out));
    scatter_and_cold<<<SCAT_BLOCKS + COLD_BLOCKS, 256>>>(polar, idx, out);
}

// round 4
// speedup vs baseline: 1.0507x; 1.0507x over previous
#include <cuda_runtime.h>
#include <cstdint>

// Problem geometry (fixed by the reference).
#define NCELLS (32 * 256 * 128)      // 1,048,576 polar cells per batch
#define NVOX   (320 * 320 * 80)      // 8,192,000 voxels per batch
#define BATCH  16
#define CPT    8

// Hot rows: every atomic target has yi in [160,287] (analytic bound from the
// polar->cartesian map: y = r*cos(el)*cos(az) in [0, 32)). With 4-voxel margin
// we zero full-x rows y in [156, 292) via cudaMemset2DAsync (223 MB).
// Cold region = rows y<156 and y>=292: two CONTIGUOUS byte spans per z-slice,
// zeroed by the TMA/bulk-copy engine concurrently with the scatter (no LSU use).
#define NSLICES    1280u                  // BATCH * 80 z-slices
#define SLICE_B    409600ull              // 320*320*4 bytes per slice
#define HOT_OFF    199680u                // 156 rows * 1280 B
#define HOT_LEN    174080u                // 136 rows * 1280 B
#define SPANA_LEN  199680u                // rows [0,156)
#define SPANB_OFF  373760u                // 292 rows * 1280 B
#define SPANB_LEN  35840u                 // rows [292,320)

#define COLD_BLOCKS 128u
#define SCAT_BLOCKS 8192u                 // 512 per batch x 16
#define CHUNK       24576u                // bulk-copy chunk = smem buffer size
#define BUF_WORDS   (24576 / 4)

__device__ __forceinline__ void bulk_zero_store(char* gdst, uint32_t saddr,
                                                unsigned len)
{
    asm volatile(
        "cp.async.bulk.global.shared::cta.bulk_group [%0], [%1], %2;"
        :: "l"((unsigned long long)(uintptr_t)gdst), "r"(saddr), "r"(len)
        : "memory");
    asm volatile("cp.async.bulk.commit_group;" ::: "memory");
}

__global__ void __launch_bounds__(256)
scatter_cold_tma(const float* __restrict__ in,
                 const int*   __restrict__ idx,
                 float*       __restrict__ out)
{
    __shared__ __align__(128) float zbuf[BUF_WORDS];

    if (blockIdx.x < COLD_BLOCKS) {
        // ---- cold role: zero rows outside the hot band via bulk-copy engine.
        for (int i = threadIdx.x; i < BUF_WORDS; i += 256) zbuf[i] = 0.f;
        __syncthreads();
        asm volatile("fence.proxy.async.shared::cta;" ::: "memory");

        if (threadIdx.x == 0) {
            uint32_t saddr = (uint32_t)__cvta_generic_to_shared(zbuf);
            unsigned issued = 0;
            for (unsigned s = blockIdx.x; s < NSLICES; s += COLD_BLOCKS) {
                char* base = (char*)out + (unsigned long long)s * SLICE_B;
                for (unsigned off = 0; off < SPANA_LEN; off += CHUNK) {
                    unsigned len = (SPANA_LEN - off < CHUNK) ? SPANA_LEN - off
                                                             : CHUNK;
                    bulk_zero_store(base + off, saddr, len);
                    if ((++issued & 15u) == 0u)
                        asm volatile("cp.async.bulk.wait_group 16;"
                                     ::: "memory");
                }
                for (unsigned off = 0; off < SPANB_LEN; off += CHUNK) {
                    unsigned len = (SPANB_LEN - off < CHUNK) ? SPANB_LEN - off
                                                             : CHUNK;
                    bulk_zero_store(base + SPANB_OFF + off, saddr, len);
                    if ((++issued & 15u) == 0u)
                        asm volatile("cp.async.bulk.wait_group 16;"
                                     ::: "memory");
                }
            }
            // Full completion (writes visible) before kernel end.
            asm volatile("cp.async.bulk.wait_group 0;" ::: "memory");
        }
        return;
    }

    // ---- scatter role: identical to the verified R1 kernel.
    unsigned sid  = blockIdx.x - COLD_BLOCKS;     // 0..8191
    unsigned b    = sid >> 9;                     // /512 -> batch
    unsigned blk  = sid & 511u;
    unsigned cell = (blk * 256u + threadIdx.x) * CPT;

    const int4* ip = reinterpret_cast<const int4*>(idx + cell);
    int4 i0 = ip[0];
    int4 i1 = ip[1];
    const float4* vp = reinterpret_cast<const float4*>(
        in + (size_t)b * NCELLS + cell);
    float4 v0 = vp[0];
    float4 v1 = vp[1];

    int   ind[CPT] = { i0.x, i0.y, i0.z, i0.w, i1.x, i1.y, i1.z, i1.w };
    float val[CPT] = { v0.x, v0.y, v0.z, v0.w, v1.x, v1.y, v1.z, v1.w };

    float* ob = out + (size_t)b * NVOX;

    // Run-length fused scatter: one RED.ADD per run of equal voxel index.
    int   cur = ind[0];
    float acc = val[0];
#pragma unroll
    for (int j = 1; j < CPT; j++) {
        if (ind[j] == cur) {
            acc += val[j];
        } else {
            atomicAdd(ob + cur, acc);             // no return -> REDG
            cur = ind[j];
            acc = val[j];
        }
    }
    atomicAdd(ob + cur, acc);
}

extern "C" void kernel_launch(void* const* d_in, const int* in_sizes, int n_in,
                              void* d_out, int out_size)
{
    const float* polar = (const float*)d_in[0];   // [16,1,32,256,128] f32
    const int*   idx   = (const int*)  d_in[1];   // [1048576] int32
    float*       out   = (float*)d_out;           // [16,1,80,320,320] f32

    // Zero the hot band only: rows y in [156,292), every z-slice. 223 MB.
    cudaMemset2DAsync((char*)out + HOT_OFF, (size_t)SLICE_B, 0,
                      (size_t)HOT_LEN, (size_t)NSLICES);

    // Fused: TMA cold-zero (blocks 0..127, scheduled first) + atomic scatter.
    scatter_cold_tma<<<COLD_BLOCKS + SCAT_BLOCKS, 256>>>(polar, idx, out);
}

// round 5
// speedup vs baseline: 1.3830x; 1.3163x over previous
#include <cuda_runtime.h>

// Problem geometry (fixed by the reference).
#define NCELLS (32 * 256 * 128)      // El*R*Az = 1,048,576 polar cells per batch
#define NVOX   (320 * 320 * 80)      // 8,192,000 voxels per batch
#define BATCH  16
#define FULLM  0xffffffffu

// One warp handles 256 consecutive cells = the az-rows (r, r+1) of one el.
// Lane t takes cells base + t + 32j (j = 0..7), so each round j covers 32
// CONTIGUOUS az cells: equal voxel indices form contiguous lane runs.
//   1) radial pair-merge: rounds j and j+4 share az at adjacent r (0.125m
//      apart vs 0.25m voxels) -> same voxel ~50% of the time; merge in regs.
//   2) per-round segmented warp scan: one RED per run of equal index,
//      emitted by the run's last lane. All-merged (zero) runs skip the RED.
// Cuts RED count ~2x; scatter is L2-atomic bound, so time scales with REDs.
__global__ void __launch_bounds__(256)
polar_scatter_agg(const float* __restrict__ in,
                  const int*   __restrict__ idx,
                  float*       __restrict__ out)
{
    unsigned warp = threadIdx.x >> 5;                  // 0..7
    unsigned lane = threadIdx.x & 31u;
    unsigned b    = blockIdx.y;
    unsigned base = (blockIdx.x * 8u + warp) * 256u;   // gridDim.x = 512

    const float* pin = in + (size_t)b * NCELLS;
    float*       ob  = out + (size_t)b * NVOX;

    int   v[8];
    float x[8];
#pragma unroll
    for (int j = 0; j < 8; j++) {
        unsigned c = base + lane + 32u * j;            // coalesced 128B/round
        v[j] = idx[c];
        x[j] = pin[c];
    }

    // Radial pair-merge: cell c (row r) vs c+128 (row r+1), same az.
#pragma unroll
    for (int j = 0; j < 4; j++) {
        if (v[j] == v[j + 4]) { x[j] += x[j + 4]; x[j + 4] = 0.f; }
    }

#pragma unroll
    for (int j = 0; j < 8; j++) {
        int   vv = v[j];
        float s  = x[j];

        int  prev = __shfl_up_sync(FULLM, vv, 1);
        bool head = (lane == 0) || (prev != vv);
        unsigned hmask = __ballot_sync(FULLM, head);

        // start lane of this lane's run = highest head bit <= lane
        unsigned below = hmask & (0xffffffffu >> (31u - lane));
        int seg = 31 - __clz(below);

        // segmented inclusive scan of s within the run
#pragma unroll
        for (int off = 1; off < 32; off <<= 1) {
            float t = __shfl_up_sync(FULLM, s, off);
            if ((int)lane - off >= seg) s += t;
        }

        bool last = (lane == 31) || ((hmask >> (lane + 1)) & 1u);
        if (last && s != 0.f)                  // s==0 <=> fully merged run
            atomicAdd(ob + vv, s);             // no return -> REDG
    }
}

extern "C" void kernel_launch(void* const* d_in, const int* in_sizes, int n_in,
                              void* d_out, int out_size)
{
    const float* polar = (const float*)d_in[0];   // [16,1,32,256,128] f32
    const int*   idx   = (const int*)  d_in[1];   // [1048576] int32
    float*       out   = (float*)d_out;           // [16,1,80,320,320] f32

    // Zero the full 524MB output (DRAM-write bound, ~77us). Overlap with the
    // scatter is provably useless: both phases consume the same LTS budget.
    cudaMemsetAsync(d_out, 0, (size_t)out_size * sizeof(float));

    dim3 grid(512, BATCH);
    polar_scatter_agg<<<grid, 256>>>(polar, idx, out);
}